// round 14
// baseline (speedup 1.0000x reference)
#include <cuda_runtime.h>
#include <cuda_fp16.h>
#include <math.h>
#include <stdint.h>

#define NS 16384
#define NB 100
#define NQ 101
#define HID 100
#define ROWSK (NS * NQ)        // 1654784
#define TILEM 128
#define NTILES (ROWSK / TILEM) // 12928 exactly
#define NKC 6                  // full k16 chunks; +1 k8 tail at col 96
#define PITCH 208              // 13*16B; 13r mod 32 distinct over 8 rows -> conflict-free
#define MLP_T 256

typedef unsigned int u32;

// ---- smem layout (byte offsets) ---------------------------------------------
#define A_BYTES (TILEM * PITCH)    // 26624
#define W_BYTES (104 * PITCH)      // 21632 (13 n8-tiles)
#define OFF_A0   0
#define OFF_A1   (A_BYTES)
#define OFF_W1   (2 * A_BYTES)
#define OFF_W2   (2 * A_BYTES + W_BYTES)
#define TILES_END (2 * A_BYTES + 2 * W_BYTES)   // 96512
#define OFF_RED  TILES_END                       // 2 parity x 2048
#define OFF_VEC  (OFF_RED + 4096)                // b1[128] b2[128] w3[128]
#define OFF_W0H  (OFF_VEC + 3 * 128 * 4)         // w0 half2[64], b0 half2[64]
#define SMEM_ALLOC (OFF_W0H + 512 + 256)         // ~100.5 KB -> 2 CTAs/SM

// ---------------- device globals (scratch) -----------------------------------
__device__ float g_ccw[NQ];
__device__ float g_csc[NQ];
__device__ float g_oh[3][2];
__device__ float g_dz[3][ROWSK];
__device__ float g_x2[NS];

// ---------------- PTX helpers (base-ISA only: ldmatrix + mma.sync) -----------
__device__ __forceinline__ u32 smem_u32(const void* p) {
    u32 a;
    asm("{ .reg .u64 t; cvta.to.shared.u64 t, %1; cvt.u32.u64 %0, t; }" : "=r"(a) : "l"(p));
    return a;
}
__device__ __forceinline__ void ldsm4(u32* r, u32 a) {
    asm volatile("ldmatrix.sync.aligned.m8n8.x4.shared.b16 {%0,%1,%2,%3}, [%4];"
                 : "=r"(r[0]), "=r"(r[1]), "=r"(r[2]), "=r"(r[3]) : "r"(a));
}
__device__ __forceinline__ void ldsm2(u32* r, u32 a) {
    asm volatile("ldmatrix.sync.aligned.m8n8.x2.shared.b16 {%0,%1}, [%2];"
                 : "=r"(r[0]), "=r"(r[1]) : "r"(a));
}
__device__ __forceinline__ void ldsm1(u32* r, u32 a) {
    asm volatile("ldmatrix.sync.aligned.m8n8.x1.shared.b16 {%0}, [%1];"
                 : "=r"(r[0]) : "r"(a));
}
__device__ __forceinline__ void mma16816(float* c, const u32* a, const u32* b) {
    asm volatile("mma.sync.aligned.m16n8k16.row.col.f32.f16.f16.f32 "
                 "{%0,%1,%2,%3}, {%4,%5,%6,%7}, {%8,%9}, {%0,%1,%2,%3};"
                 : "+f"(c[0]), "+f"(c[1]), "+f"(c[2]), "+f"(c[3])
                 : "r"(a[0]), "r"(a[1]), "r"(a[2]), "r"(a[3]), "r"(b[0]), "r"(b[1]));
}
__device__ __forceinline__ void mma1688(float* c, const u32* a, const u32* b) {
    asm volatile("mma.sync.aligned.m16n8k8.row.col.f32.f16.f16.f32 "
                 "{%0,%1,%2,%3}, {%4,%5}, {%6}, {%0,%1,%2,%3};"
                 : "+f"(c[0]), "+f"(c[1]), "+f"(c[2]), "+f"(c[3])
                 : "r"(a[0]), "r"(a[1]), "r"(b[0]));
}
// half-CTA barrier: 128 threads of one wm group (threads 0-127 or 128-255)
__device__ __forceinline__ void bar_half(int wm) {
    asm volatile("bar.sync %0, 128;" :: "r"(1 + wm) : "memory");
}

__device__ __forceinline__ unsigned short h_bits(float f) {
    __half h = __float2half_rn(f);
    return *reinterpret_cast<unsigned short*>(&h);
}
__device__ __forceinline__ u32 pack_hi(float f0, float f1) {
    return (u32)h_bits(f0) | ((u32)h_bits(f1) << 16);
}

// ---------------- setup: 4 blocks (CC quadrature + 3x oh constants) ----------
__global__ void setup_kernel(const float* __restrict__ hb0,
                             const float* __restrict__ hW1,
                             const float* __restrict__ hb1,
                             const float* __restrict__ hW2,
                             const float* __restrict__ hb2,
                             const float* __restrict__ hW3,
                             const float* __restrict__ hb3)
{
    const double PI = 3.14159265358979323846;
    int t = threadIdx.x;

    if (blockIdx.x == 0) {
        if (t < NQ) {
            double acc = 0.0;
            for (int i = 0; i <= NB; i++) {
                double lij = cos((double)i * (double)t * PI / (double)NB);
                if (t == 0)  lij = 0.5;
                if (t == NB) lij *= 0.5;
                double Wi;
                if (i == 0)      Wi = 1.0;
                else if (i & 1)  Wi = 0.0;
                else             Wi = 2.0 / (1.0 - (double)i * (double)i);
                acc += lij * Wi;
            }
            g_ccw[t] = (float)(acc * 2.0 / (double)NB);
            g_csc[t] = (float)((cos((double)t * PI / (double)NB) + 1.0) * 0.5);
        }
        return;
    }

    int k = blockIdx.x - 1;
    __shared__ float hA[HID], hB[HID];
    if (t < HID) hA[t] = fmaxf(hb0[k * HID + t], 0.f);
    __syncthreads();
    if (t < HID) {
        float s = hb1[k * HID + t];
        for (int i = 0; i < HID; i++) s += hW1[(k * HID + t) * HID + i] * hA[i];
        hB[t] = fmaxf(s, 0.f);
    }
    __syncthreads();
    if (t < HID) {
        float s = hb2[k * HID + t];
        for (int i = 0; i < HID; i++) s += hW2[(k * HID + t) * HID + i] * hB[i];
        hA[t] = fmaxf(s, 0.f);
    }
    __syncthreads();
    if (t < 2) {
        float s = hb3[k * 2 + t];
        for (int i = 0; i < HID; i++) s += hW3[(k * 2 + t) * HID + i] * hA[i];
        g_oh[k][t] = s;
    }
}

// ---------------- tensor-core MLP kernel (fp16 mma.sync, 2 CTAs/SM) ----------
// A double-buffered (A0: layer-0 out, A1: layer-1 out) -> no WAR barrier.
// All loop barriers are half-CTA (bar.sync id,128); halves fully decoupled.
__global__ __launch_bounds__(MLP_T, 2)
void mlp_tc(const float* __restrict__ xin, int kbase,
            const float* __restrict__ iW0, const float* __restrict__ ib0,
            const float* __restrict__ iW1, const float* __restrict__ ib1,
            const float* __restrict__ iW2, const float* __restrict__ ib2,
            const float* __restrict__ iW3, const float* __restrict__ ib3,
            float* __restrict__ dzbase)
{
    extern __shared__ char ab[];
    const u32 sm = smem_u32(ab);

    const int tid  = threadIdx.x;
    const int lane = tid & 31;
    const int wid  = tid >> 5;
    const int wm   = wid >> 2;   // 0..1  (M group; threads [wm*128, wm*128+128))
    const int wn   = wid & 3;    // 0..3  (SMSP index)
    const int k    = kbase + blockIdx.y;

    // zero A0/A1/W buffers (establishes K/N pads)
    for (int i = tid; i < TILES_END / 16; i += MLP_T)
        reinterpret_cast<uint4*>(ab)[i] = make_uint4(0, 0, 0, 0);

    float*   redv = (float*)(ab + OFF_RED);   // [2][128][4]
    float*   b1v  = (float*)(ab + OFF_VEC);
    float*   b2v  = b1v + 128;
    float*   w3v  = b2v + 128;
    __half2* w0h  = (__half2*)(ab + OFF_W0H); // [64]
    __half2* b0h  = w0h + 64;                 // [64]
    __syncthreads();

    for (int i = tid; i < 128; i += MLP_T) {
        b1v[i] = (i < HID) ? ib1[k * HID + i] : 0.f;
        b2v[i] = (i < HID) ? ib2[k * HID + i] : 0.f;
        w3v[i] = (i < HID) ? iW3[k * HID + i] : 0.f;
    }
    if (tid < 64) {
        int c0 = 2 * tid, c1 = 2 * tid + 1;
        float w0a = (c0 < HID) ? iW0[(k * HID + c0) * 3] : 0.f;  // h==0: input col 0 only
        float w0b = (c1 < HID) ? iW0[(k * HID + c1) * 3] : 0.f;
        float b0a = (c0 < HID) ? ib0[k * HID + c0] : 0.f;
        float b0b = (c1 < HID) ? ib0[k * HID + c1] : 0.f;
        w0h[tid] = __floats2half2_rn(w0a, w0b);
        b0h[tid] = __floats2half2_rn(b0a, b0b);
    }
    // stage W1/W2 (fp16) as [N][K], pitch 208B
    for (int idx = tid; idx < HID * HID; idx += MLP_T) {
        int o = idx / HID, i = idx % HID;
        u32 off = o * PITCH + i * 2;
        *(unsigned short*)(ab + OFF_W1 + off) = h_bits(iW1[(k * HID + o) * HID + i]);
        *(unsigned short*)(ab + OFF_W2 + off) = h_bits(iW2[(k * HID + o) * HID + i]);
    }
    __syncthreads();

    // lane-dependent ldmatrix address terms
    const u32 a_l  = (u32)((lane & 15) * PITCH + ((lane >> 4) & 1) * 16);  // k16 A (x4)
    const u32 a_l2 = (u32)((lane & 15) * PITCH + 192);                     // k8 tail A (x2)
    const u32 b4_l = (u32)((lane & 7) * PITCH + ((lane >> 3) & 1) * 16
                           + ((lane >> 4) & 1) * (8 * PITCH));             // k16 B pair (x4)
    const u32 b2_l = (u32)((lane & 7) * PITCH + ((lane >> 3) & 1) * 16);   // k16 B single (x2)
    const u32 bt2_l = (u32)((lane & 7) * PITCH + 192
                            + ((lane >> 3) & 1) * (8 * PITCH));            // k8 tail B pair (x2)
    const u32 bt1_l = (u32)((lane & 7) * PITCH + 192);                     // k8 tail B single (x1)

    const float b3 = ib3[k];
    const __half2 hz = __float2half2_rn(0.f);

    int par = 0;
    for (int tile = blockIdx.x; tile < NTILES; tile += gridDim.x, par ^= 1) {
        float* redp = redv + par * 512;

        // ---- layer 0: scalar -> 100, packed half2 math, vector stores to A0 ----
        {
            int r0 = tid >> 1;
            int row = tile * TILEM + r0;
            int n = row / NQ, j = row - n * NQ;
            __half2 s2 = __float2half2_rn(xin[n] * g_csc[j]);
            char* a0 = ab + OFF_A0 + r0 * PITCH;
            if ((tid & 1) == 0) {
                #pragma unroll
                for (int q = 0; q < 6; q++) {
                    u32 t0[4];
                    #pragma unroll
                    for (int e = 0; e < 4; e++) {
                        __half2 v = __hmax2(__hfma2(w0h[q * 4 + e], s2, b0h[q * 4 + e]), hz);
                        t0[e] = *(u32*)&v;
                    }
                    *(uint4*)(a0 + q * 16) = make_uint4(t0[0], t0[1], t0[2], t0[3]);
                }
            } else {
                #pragma unroll
                for (int q = 0; q < 6; q++) {
                    u32 t0[4];
                    #pragma unroll
                    for (int e = 0; e < 4; e++) {
                        __half2 v = __hmax2(__hfma2(w0h[24 + q * 4 + e], s2, b0h[24 + q * 4 + e]), hz);
                        t0[e] = *(u32*)&v;
                    }
                    *(uint4*)(a0 + 96 + q * 16) = make_uint4(t0[0], t0[1], t0[2], t0[3]);
                }
                __half2 v0 = __hmax2(__hfma2(w0h[48], s2, b0h[48]), hz);
                __half2 v1 = __hmax2(__hfma2(w0h[49], s2, b0h[49]), hz);
                *(uint2*)(a0 + 192) = make_uint2(*(u32*)&v0, *(u32*)&v1);
            }
        }
        bar_half(wm);   // A0 rows of this half ready

        // ---- layers 1 & 2 via mma.sync ----
        for (int L = 0; L < 2; L++) {
            const u32 sW = sm + (L ? OFF_W2 : OFF_W1);
            const u32 sAbuf = sm + (L ? OFF_A1 : OFF_A0);

            // rotated N-partition for SMSP balance
            const int part = (wn + wm + 2 * L) & 3;
            const int nt0  = (part == 0) ? 0 : (1 + 3 * part);
            const int ncnt = (part == 0) ? 4 : 3;

            float acc[4][4][4];
            #pragma unroll
            for (int mi = 0; mi < 4; mi++)
                #pragma unroll
                for (int ni = 0; ni < 4; ni++)
                    #pragma unroll
                    for (int e = 0; e < 4; e++) acc[mi][ni][e] = 0.f;

            #pragma unroll
            for (int kc = 0; kc < NKC; kc++) {
                u32 ah[4][4], bh[4][2];
                #pragma unroll
                for (int mi = 0; mi < 4; mi++) {
                    u32 aoff = (u32)((wm * 4 + mi) * (16 * PITCH) + kc * 32) + a_l;
                    ldsm4(ah[mi], sAbuf + aoff);
                }
                // B: pair loads via ldsm4 (2 n-tiles per instruction)
                ldsm4(&bh[0][0], sW + (u32)(nt0 * (8 * PITCH) + kc * 32) + b4_l);
                if (ncnt == 4)
                    ldsm4(&bh[2][0], sW + (u32)((nt0 + 2) * (8 * PITCH) + kc * 32) + b4_l);
                else
                    ldsm2(&bh[2][0], sW + (u32)((nt0 + 2) * (8 * PITCH) + kc * 32) + b2_l);
                #pragma unroll
                for (int mi = 0; mi < 4; mi++)
                    #pragma unroll
                    for (int ni = 0; ni < 4; ni++)
                        if (ni < ncnt)
                            mma16816(acc[mi][ni], ah[mi], bh[ni]);
            }
            // k8 tail: cols 96..103 (100..103 are zero padding)
            {
                u32 at[4][2], bt[4][1];
                #pragma unroll
                for (int mi = 0; mi < 4; mi++) {
                    u32 aoff = (u32)((wm * 4 + mi) * (16 * PITCH)) + a_l2;
                    ldsm2(at[mi], sAbuf + aoff);
                }
                u32 btp[2];
                ldsm2(btp, sW + (u32)(nt0 * (8 * PITCH)) + bt2_l);
                bt[0][0] = btp[0]; bt[1][0] = btp[1];
                if (ncnt == 4) {
                    ldsm2(btp, sW + (u32)((nt0 + 2) * (8 * PITCH)) + bt2_l);
                    bt[2][0] = btp[0]; bt[3][0] = btp[1];
                } else {
                    ldsm1(&bt[2][0], sW + (u32)((nt0 + 2) * (8 * PITCH)) + bt1_l);
                }
                #pragma unroll
                for (int mi = 0; mi < 4; mi++)
                    #pragma unroll
                    for (int ni = 0; ni < 4; ni++)
                        if (ni < ncnt)
                            mma1688(acc[mi][ni], at[mi], bt[ni]);
            }

            if (L == 0) {
                // epilogue: bias + relu, fp16, write to A1 (no WAR barrier needed)
                #pragma unroll
                for (int mi = 0; mi < 4; mi++) {
                    int r0 = (wm * 4 + mi) * 16 + (lane >> 2);
                    #pragma unroll
                    for (int ni = 0; ni < 4; ni++) {
                        int c0 = (nt0 + ni) * 8 + (lane & 3) * 2;
                        if (ni < ncnt && c0 < HID) {
                            float bb0 = b1v[c0], bb1 = b1v[c0 + 1];
                            float v0 = fmaxf(acc[mi][ni][0] + bb0, 0.f);
                            float v1 = fmaxf(acc[mi][ni][1] + bb1, 0.f);
                            float v2 = fmaxf(acc[mi][ni][2] + bb0, 0.f);
                            float v3 = fmaxf(acc[mi][ni][3] + bb1, 0.f);
                            *(u32*)(ab + OFF_A1 + r0 * PITCH + c0 * 2)       = pack_hi(v0, v1);
                            *(u32*)(ab + OFF_A1 + (r0 + 8) * PITCH + c0 * 2) = pack_hi(v2, v3);
                        }
                    }
                }
                bar_half(wm);   // A1 rows of this half ready for L2 ldsm
            } else {
                // layer 3: weighted partial dot per thread, warp shfl, smem reduce
                float rp[4][2];
                #pragma unroll
                for (int mi = 0; mi < 4; mi++) { rp[mi][0] = 0.f; rp[mi][1] = 0.f; }
                #pragma unroll
                for (int ni = 0; ni < 4; ni++) {
                    int c0 = (nt0 + ni) * 8 + (lane & 3) * 2;
                    if (ni < ncnt && c0 < HID) {
                        float bb0 = b2v[c0], bb1 = b2v[c0 + 1];
                        float w30 = w3v[c0], w31 = w3v[c0 + 1];
                        #pragma unroll
                        for (int mi = 0; mi < 4; mi++) {
                            float v0 = fmaxf(acc[mi][ni][0] + bb0, 0.f);
                            float v1 = fmaxf(acc[mi][ni][1] + bb1, 0.f);
                            float v2 = fmaxf(acc[mi][ni][2] + bb0, 0.f);
                            float v3 = fmaxf(acc[mi][ni][3] + bb1, 0.f);
                            rp[mi][0] = fmaf(w30, v0, fmaf(w31, v1, rp[mi][0]));
                            rp[mi][1] = fmaf(w30, v2, fmaf(w31, v3, rp[mi][1]));
                        }
                    }
                }
                #pragma unroll
                for (int mi = 0; mi < 4; mi++) {
                    #pragma unroll
                    for (int e = 0; e < 2; e++) {
                        rp[mi][e] += __shfl_xor_sync(0xffffffffu, rp[mi][e], 1);
                        rp[mi][e] += __shfl_xor_sync(0xffffffffu, rp[mi][e], 2);
                    }
                }
                if ((lane & 3) == 0) {
                    #pragma unroll
                    for (int mi = 0; mi < 4; mi++) {
                        int r0 = (wm * 4 + mi) * 16 + (lane >> 2);
                        redp[r0 * 4 + wn] = rp[mi][0];
                        redp[(r0 + 8) * 4 + wn] = rp[mi][1];
                    }
                }
                bar_half(wm);   // redv rows of this half complete (written by own-half warps)
                {
                    int t7 = tid & 127;
                    if (t7 < 64) {
                        int r = wm * 64 + t7;         // own-half row
                        int row = tile * TILEM + r;
                        int j = row % NQ;
                        float out = redp[r * 4] + redp[r * 4 + 1]
                                  + redp[r * 4 + 2] + redp[r * 4 + 3] + b3;
                        float dz = (out > 0.f) ? (out + 1.f) : expf(out);
                        dzbase[(size_t)k * ROWSK + row] = dz * g_ccw[j];
                    }
                }
                // no trailing sync: redv parity buffer protects reuse
            }
        }
    }
}

// ---------------- reduction: warp per sample; blockIdx.y picks stream --------
__global__ void reduce_pair(const float* __restrict__ dzA, const float* __restrict__ xA,
                            int kA, float* __restrict__ dstA,
                            const float* __restrict__ dzB, const float* __restrict__ xB,
                            int kB, float* __restrict__ dstB)
{
    const float* dzk = (blockIdx.y == 0) ? dzA : dzB;
    const float* xin = (blockIdx.y == 0) ? xA : xB;
    float* dst       = (blockIdx.y == 0) ? dstA : dstB;
    int k            = (blockIdx.y == 0) ? kA : kB;

    int n = blockIdx.x * (blockDim.x >> 5) + (threadIdx.x >> 5);
    int lane = threadIdx.x & 31;
    if (n >= NS) return;
    const float* p = dzk + (size_t)n * NQ;
    float s = 0.f;
    for (int j = lane; j < NQ; j += 32) s += p[j];
    #pragma unroll
    for (int o = 16; o; o >>= 1) s += __shfl_xor_sync(0xffffffffu, s, o);
    if (lane == 0) {
        float z = s * xin[n] * 0.5f;
        dst[n] = expf(g_oh[k][1]) * z + g_oh[k][0];
    }
}

// ---------------- launch -----------------------------------------------------
extern "C" void kernel_launch(void* const* d_in, const int* in_sizes, int n_in,
                              void* d_out, int out_size)
{
    const float* logits = (const float*)d_in[0];
    const float* iW0 = (const float*)d_in[2];
    const float* ib0 = (const float*)d_in[3];
    const float* iW1 = (const float*)d_in[4];
    const float* ib1 = (const float*)d_in[5];
    const float* iW2 = (const float*)d_in[6];
    const float* ib2 = (const float*)d_in[7];
    const float* iW3 = (const float*)d_in[8];
    const float* ib3 = (const float*)d_in[9];
    const float* hb0 = (const float*)d_in[11];
    const float* hW1 = (const float*)d_in[12];
    const float* hb1 = (const float*)d_in[13];
    const float* hW2 = (const float*)d_in[14];
    const float* hb2 = (const float*)d_in[15];
    const float* hW3 = (const float*)d_in[16];
    const float* hb3 = (const float*)d_in[17];

    float* out = (float*)d_out;

    void *dz_addr = nullptr, *x2_addr = nullptr;
    cudaGetSymbolAddress(&dz_addr, g_dz);
    cudaGetSymbolAddress(&x2_addr, g_x2);
    float* dz = (float*)dz_addr;
    float* x2 = (float*)x2_addr;

    cudaFuncSetAttribute(mlp_tc, cudaFuncAttributeMaxDynamicSharedMemorySize, SMEM_ALLOC);

    // 1) constants (4 parallel blocks)
    setup_kernel<<<4, 128>>>(hb0, hW1, hb1, hW2, hb2, hW3, hb3);

    // 2) networks 0 and 1 on x1 = logits (2 CTAs/SM resident)
    dim3 g1(148, 2);
    mlp_tc<<<g1, MLP_T, SMEM_ALLOC>>>(logits, 0,
                                      iW0, ib0, iW1, ib1, iW2, ib2, iW3, ib3, dz);

    // 3) fused reduce: k=0 -> x2 and k=1 -> y1
    const int RWARPS = 8;
    dim3 gr((NS + RWARPS - 1) / RWARPS, 2);
    reduce_pair<<<gr, RWARPS * 32>>>(dz + 0 * (size_t)ROWSK, logits, 0, x2,
                                     dz + 1 * (size_t)ROWSK, logits, 1, out);

    // 4) network 2 on x2 (fill both CTA slots per SM)
    dim3 g2(296, 1);
    mlp_tc<<<g2, MLP_T, SMEM_ALLOC>>>(x2, 2,
                                      iW0, ib0, iW1, ib1, iW2, ib2, iW3, ib3, dz);

    // 5) reduce k=2 -> y2
    dim3 gr2((NS + RWARPS - 1) / RWARPS, 1);
    reduce_pair<<<gr2, RWARPS * 32>>>(dz + 2 * (size_t)ROWSK, x2, 2, out + NS,
                                      dz + 2 * (size_t)ROWSK, x2, 2, out + NS);

    // 6) pass-through logits
    cudaMemcpyAsync(out + 2 * NS, logits, NS * sizeof(float), cudaMemcpyDeviceToDevice);
}

// round 16
// speedup vs baseline: 1.0480x; 1.0480x over previous
#include <cuda_runtime.h>
#include <cuda_fp16.h>
#include <math.h>
#include <stdint.h>

#define NS 16384
#define NB 100
#define NQ 101
#define HID 100
#define ROWSK (NS * NQ)        // 1654784
#define TILEM 128
#define NTILES (ROWSK / TILEM) // 12928 exactly
#define NKC 6                  // full k16 chunks; +1 k8 tail at col 96
#define PITCH 208              // 13*16B; conflict-free for LDSM
#define MLP_T 256

typedef unsigned int u32;

// ---- smem layout (byte offsets) ---------------------------------------------
#define A_BYTES (TILEM * PITCH)    // 26624
#define W_BYTES (104 * PITCH)      // 21632 (13 n8-tiles)
#define OFF_A0   0
#define OFF_A1   (A_BYTES)
#define OFF_W1   (2 * A_BYTES)
#define OFF_W2   (2 * A_BYTES + W_BYTES)
#define TILES_END (2 * A_BYTES + 2 * W_BYTES)   // 96512
#define OFF_RED  TILES_END                       // 2 parity x 1024
#define OFF_VEC  (OFF_RED + 2048)                // b1[128] b2[128] w3[128]
#define OFF_W0H  (OFF_VEC + 3 * 128 * 4)         // w0 half2[64], b0 half2[64]
#define SMEM_ALLOC (OFF_W0H + 512 + 256)         // ~99 KB -> 2 CTAs/SM

// ---------------- device globals (scratch) -----------------------------------
__device__ float g_ccw[NQ];
__device__ float g_csc[NQ];
__device__ float g_oh[3][2];
__device__ float g_dz[3][ROWSK];
__device__ float g_x2[NS];

// ---------------- PTX helpers (base-ISA only: ldmatrix + mma.sync) -----------
__device__ __forceinline__ u32 smem_u32(const void* p) {
    u32 a;
    asm("{ .reg .u64 t; cvta.to.shared.u64 t, %1; cvt.u32.u64 %0, t; }" : "=r"(a) : "l"(p));
    return a;
}
__device__ __forceinline__ void ldsm4(u32* r, u32 a) {
    asm volatile("ldmatrix.sync.aligned.m8n8.x4.shared.b16 {%0,%1,%2,%3}, [%4];"
                 : "=r"(r[0]), "=r"(r[1]), "=r"(r[2]), "=r"(r[3]) : "r"(a));
}
__device__ __forceinline__ void ldsm2(u32* r, u32 a) {
    asm volatile("ldmatrix.sync.aligned.m8n8.x2.shared.b16 {%0,%1}, [%2];"
                 : "=r"(r[0]), "=r"(r[1]) : "r"(a));
}
__device__ __forceinline__ void ldsm1(u32* r, u32 a) {
    asm volatile("ldmatrix.sync.aligned.m8n8.x1.shared.b16 {%0}, [%1];"
                 : "=r"(r[0]) : "r"(a));
}
__device__ __forceinline__ void mma16816(float* c, const u32* a, const u32* b) {
    asm volatile("mma.sync.aligned.m16n8k16.row.col.f32.f16.f16.f32 "
                 "{%0,%1,%2,%3}, {%4,%5,%6,%7}, {%8,%9}, {%0,%1,%2,%3};"
                 : "+f"(c[0]), "+f"(c[1]), "+f"(c[2]), "+f"(c[3])
                 : "r"(a[0]), "r"(a[1]), "r"(a[2]), "r"(a[3]), "r"(b[0]), "r"(b[1]));
}
__device__ __forceinline__ void mma1688(float* c, const u32* a, const u32* b) {
    asm volatile("mma.sync.aligned.m16n8k8.row.col.f32.f16.f16.f32 "
                 "{%0,%1,%2,%3}, {%4,%5}, {%6}, {%0,%1,%2,%3};"
                 : "+f"(c[0]), "+f"(c[1]), "+f"(c[2]), "+f"(c[3])
                 : "r"(a[0]), "r"(a[1]), "r"(b[0]));
}
// quarter-CTA barrier: 64 threads of one M-group (warps 2q, 2q+1)
__device__ __forceinline__ void bar_q(int wq) {
    asm volatile("bar.sync %0, 64;" :: "r"(1 + wq) : "memory");
}

__device__ __forceinline__ unsigned short h_bits(float f) {
    __half h = __float2half_rn(f);
    return *reinterpret_cast<unsigned short*>(&h);
}
__device__ __forceinline__ u32 pack_hi(float f0, float f1) {
    return (u32)h_bits(f0) | ((u32)h_bits(f1) << 16);
}

// ---------------- setup: 4 blocks (CC quadrature + 3x oh constants) ----------
__global__ void setup_kernel(const float* __restrict__ hb0,
                             const float* __restrict__ hW1,
                             const float* __restrict__ hb1,
                             const float* __restrict__ hW2,
                             const float* __restrict__ hb2,
                             const float* __restrict__ hW3,
                             const float* __restrict__ hb3)
{
    const double PI = 3.14159265358979323846;
    int t = threadIdx.x;

    if (blockIdx.x == 0) {
        if (t < NQ) {
            double acc = 0.0;
            for (int i = 0; i <= NB; i++) {
                double lij = cos((double)i * (double)t * PI / (double)NB);
                if (t == 0)  lij = 0.5;
                if (t == NB) lij *= 0.5;
                double Wi;
                if (i == 0)      Wi = 1.0;
                else if (i & 1)  Wi = 0.0;
                else             Wi = 2.0 / (1.0 - (double)i * (double)i);
                acc += lij * Wi;
            }
            g_ccw[t] = (float)(acc * 2.0 / (double)NB);
            g_csc[t] = (float)((cos((double)t * PI / (double)NB) + 1.0) * 0.5);
        }
        return;
    }

    int k = blockIdx.x - 1;
    __shared__ float hA[HID], hB[HID];
    if (t < HID) hA[t] = fmaxf(hb0[k * HID + t], 0.f);
    __syncthreads();
    if (t < HID) {
        float s = hb1[k * HID + t];
        for (int i = 0; i < HID; i++) s += hW1[(k * HID + t) * HID + i] * hA[i];
        hB[t] = fmaxf(s, 0.f);
    }
    __syncthreads();
    if (t < HID) {
        float s = hb2[k * HID + t];
        for (int i = 0; i < HID; i++) s += hW2[(k * HID + t) * HID + i] * hB[i];
        hA[t] = fmaxf(s, 0.f);
    }
    __syncthreads();
    if (t < 2) {
        float s = hb3[k * 2 + t];
        for (int i = 0; i < HID; i++) s += hW3[(k * 2 + t) * HID + i] * hA[i];
        g_oh[k][t] = s;
    }
}

// ---------------- tensor-core MLP kernel (fp16 mma.sync, 2 CTAs/SM) ----------
// Warp grid 4(M) x 2(N): wm = wid>>1 owns rows [wm*32, wm*32+32); the two warps
// of an M-group take N halves 7/6 n8-tiles, rotated per layer for SMSP balance.
// All in-loop ordering is quarter-CTA (bar.sync id,64): 8 pipelines per SM.
__global__ __launch_bounds__(MLP_T, 2)
void mlp_tc(const float* __restrict__ xin, int kbase,
            const float* __restrict__ iW0, const float* __restrict__ ib0,
            const float* __restrict__ iW1, const float* __restrict__ ib1,
            const float* __restrict__ iW2, const float* __restrict__ ib2,
            const float* __restrict__ iW3, const float* __restrict__ ib3,
            float* __restrict__ dzbase)
{
    extern __shared__ char ab[];
    const u32 sm = smem_u32(ab);

    const int tid  = threadIdx.x;
    const int lane = tid & 31;
    const int wid  = tid >> 5;
    const int wm   = wid >> 1;   // 0..3  (M group; rows [wm*32, wm*32+32))
    const int wnl  = wid & 1;    // 0..1  (N half selector base)
    const int k    = kbase + blockIdx.y;

    // zero A0/A1/W buffers (establishes K/N pads)
    for (int i = tid; i < TILES_END / 16; i += MLP_T)
        reinterpret_cast<uint4*>(ab)[i] = make_uint4(0, 0, 0, 0);

    float*   redv = (float*)(ab + OFF_RED);   // [2][128][2]
    float*   b1v  = (float*)(ab + OFF_VEC);
    float*   b2v  = b1v + 128;
    float*   w3v  = b2v + 128;
    __half2* w0h  = (__half2*)(ab + OFF_W0H); // [64]
    __half2* b0h  = w0h + 64;                 // [64]
    __syncthreads();

    for (int i = tid; i < 128; i += MLP_T) {
        b1v[i] = (i < HID) ? ib1[k * HID + i] : 0.f;
        b2v[i] = (i < HID) ? ib2[k * HID + i] : 0.f;
        w3v[i] = (i < HID) ? iW3[k * HID + i] : 0.f;
    }
    if (tid < 64) {
        int c0 = 2 * tid, c1 = 2 * tid + 1;
        float w0a = (c0 < HID) ? iW0[(k * HID + c0) * 3] : 0.f;  // h==0: input col 0 only
        float w0b = (c1 < HID) ? iW0[(k * HID + c1) * 3] : 0.f;
        float b0a = (c0 < HID) ? ib0[k * HID + c0] : 0.f;
        float b0b = (c1 < HID) ? ib0[k * HID + c1] : 0.f;
        w0h[tid] = __floats2half2_rn(w0a, w0b);
        b0h[tid] = __floats2half2_rn(b0a, b0b);
    }
    // stage W1/W2 (fp16) as [N][K], pitch 208B
    for (int idx = tid; idx < HID * HID; idx += MLP_T) {
        int o = idx / HID, i = idx % HID;
        u32 off = o * PITCH + i * 2;
        *(unsigned short*)(ab + OFF_W1 + off) = h_bits(iW1[(k * HID + o) * HID + i]);
        *(unsigned short*)(ab + OFF_W2 + off) = h_bits(iW2[(k * HID + o) * HID + i]);
    }
    __syncthreads();

    // lane-dependent ldmatrix address terms
    const u32 a_l  = (u32)((lane & 15) * PITCH + ((lane >> 4) & 1) * 16);  // k16 A (x4)
    const u32 a_l2 = (u32)((lane & 15) * PITCH + 192);                     // k8 tail A (x2)
    const u32 b4_l = (u32)((lane & 7) * PITCH + ((lane >> 3) & 1) * 16
                           + ((lane >> 4) & 1) * (8 * PITCH));             // k16 B pair (x4)
    const u32 b2_l = (u32)((lane & 7) * PITCH + ((lane >> 3) & 1) * 16);   // k16 B single (x2)
    const u32 bt2_l = (u32)((lane & 7) * PITCH + 192
                            + ((lane >> 3) & 1) * (8 * PITCH));            // k8 tail B pair (x2)
    const u32 bt1_l = (u32)((lane & 7) * PITCH + 192);                     // k8 tail B single (x1)

    const float b3 = ib3[k];
    const __half2 hz = __float2half2_rn(0.f);
    const int t6 = tid & 63;

    int par = 0;
    for (int tile = blockIdx.x; tile < NTILES; tile += gridDim.x, par ^= 1) {
        float* redp = redv + par * 256;

        // ---- layer 0: scalar -> 100, packed half2 math; own quarter's 32 rows ----
        {
            int r0 = wm * 32 + (t6 >> 1);
            int row = tile * TILEM + r0;
            int n = row / NQ, j = row - n * NQ;
            __half2 s2 = __float2half2_rn(xin[n] * g_csc[j]);
            char* a0 = ab + OFF_A0 + r0 * PITCH;
            if ((tid & 1) == 0) {
                #pragma unroll
                for (int q = 0; q < 6; q++) {
                    u32 t0[4];
                    #pragma unroll
                    for (int e = 0; e < 4; e++) {
                        __half2 v = __hmax2(__hfma2(w0h[q * 4 + e], s2, b0h[q * 4 + e]), hz);
                        t0[e] = *(u32*)&v;
                    }
                    *(uint4*)(a0 + q * 16) = make_uint4(t0[0], t0[1], t0[2], t0[3]);
                }
            } else {
                #pragma unroll
                for (int q = 0; q < 6; q++) {
                    u32 t0[4];
                    #pragma unroll
                    for (int e = 0; e < 4; e++) {
                        __half2 v = __hmax2(__hfma2(w0h[24 + q * 4 + e], s2, b0h[24 + q * 4 + e]), hz);
                        t0[e] = *(u32*)&v;
                    }
                    *(uint4*)(a0 + 96 + q * 16) = make_uint4(t0[0], t0[1], t0[2], t0[3]);
                }
                __half2 v0 = __hmax2(__hfma2(w0h[48], s2, b0h[48]), hz);
                __half2 v1 = __hmax2(__hfma2(w0h[49], s2, b0h[49]), hz);
                *(uint2*)(a0 + 192) = make_uint2(*(u32*)&v0, *(u32*)&v1);
            }
        }
        bar_q(wm);   // this quarter's A0 rows ready

        // ---- layers 1 & 2 via mma.sync ----
        for (int L = 0; L < 2; L++) {
            const u32 sW = sm + (L ? OFF_W2 : OFF_W1);
            const u32 sAbuf = sm + (L ? OFF_A1 : OFF_A0);

            // N-half rotated per layer: nsel=0 -> tiles [0,7), nsel=1 -> [7,13)
            const int nsel = (wnl ^ L) & 1;
            const int nt0  = nsel * 7;
            const int cnt  = 7 - nsel;   // 7 or 6

            float acc[2][7][4];
            #pragma unroll
            for (int mi = 0; mi < 2; mi++)
                #pragma unroll
                for (int ni = 0; ni < 7; ni++)
                    #pragma unroll
                    for (int e = 0; e < 4; e++) acc[mi][ni][e] = 0.f;

            #pragma unroll
            for (int kc = 0; kc < NKC; kc++) {
                u32 ah[2][4], bh[7][2];
                #pragma unroll
                for (int mi = 0; mi < 2; mi++) {
                    u32 aoff = (u32)((wm * 2 + mi) * (16 * PITCH) + kc * 32) + a_l;
                    ldsm4(ah[mi], sAbuf + aoff);
                }
                #pragma unroll
                for (int p = 0; p < 3; p++)
                    ldsm4(&bh[2 * p][0], sW + (u32)((nt0 + 2 * p) * (8 * PITCH) + kc * 32) + b4_l);
                if (cnt == 7)
                    ldsm2(&bh[6][0], sW + (u32)((nt0 + 6) * (8 * PITCH) + kc * 32) + b2_l);
                #pragma unroll
                for (int mi = 0; mi < 2; mi++)
                    #pragma unroll
                    for (int ni = 0; ni < 7; ni++)
                        if (ni < cnt)
                            mma16816(acc[mi][ni], ah[mi], bh[ni]);
            }
            // k8 tail: cols 96..103 (100..103 are zero padding)
            {
                u32 at[2][2], bt[7][1];
                #pragma unroll
                for (int mi = 0; mi < 2; mi++) {
                    u32 aoff = (u32)((wm * 2 + mi) * (16 * PITCH)) + a_l2;
                    ldsm2(at[mi], sAbuf + aoff);
                }
                #pragma unroll
                for (int p = 0; p < 3; p++) {
                    u32 btp[2];
                    ldsm2(btp, sW + (u32)((nt0 + 2 * p) * (8 * PITCH)) + bt2_l);
                    bt[2 * p][0] = btp[0]; bt[2 * p + 1][0] = btp[1];
                }
                if (cnt == 7)
                    ldsm1(&bt[6][0], sW + (u32)((nt0 + 6) * (8 * PITCH)) + bt1_l);
                #pragma unroll
                for (int mi = 0; mi < 2; mi++)
                    #pragma unroll
                    for (int ni = 0; ni < 7; ni++)
                        if (ni < cnt)
                            mma1688(acc[mi][ni], at[mi], bt[ni]);
            }

            if (L == 0) {
                // epilogue: bias + relu, fp16, write to A1 (own quarter rows)
                #pragma unroll
                for (int mi = 0; mi < 2; mi++) {
                    int r0 = (wm * 2 + mi) * 16 + (lane >> 2);
                    #pragma unroll
                    for (int ni = 0; ni < 7; ni++) {
                        int c0 = (nt0 + ni) * 8 + (lane & 3) * 2;
                        if (ni < cnt && c0 < HID) {
                            float bb0 = b1v[c0], bb1 = b1v[c0 + 1];
                            float v0 = fmaxf(acc[mi][ni][0] + bb0, 0.f);
                            float v1 = fmaxf(acc[mi][ni][1] + bb1, 0.f);
                            float v2 = fmaxf(acc[mi][ni][2] + bb0, 0.f);
                            float v3 = fmaxf(acc[mi][ni][3] + bb1, 0.f);
                            *(u32*)(ab + OFF_A1 + r0 * PITCH + c0 * 2)       = pack_hi(v0, v1);
                            *(u32*)(ab + OFF_A1 + (r0 + 8) * PITCH + c0 * 2) = pack_hi(v2, v3);
                        }
                    }
                }
                bar_q(wm);   // this quarter's A1 rows ready for L2 ldsm
            } else {
                // layer 3: weighted partial dot per thread, warp shfl, smem reduce
                float rp[2][2];
                rp[0][0] = rp[0][1] = rp[1][0] = rp[1][1] = 0.f;
                #pragma unroll
                for (int ni = 0; ni < 7; ni++) {
                    int c0 = (nt0 + ni) * 8 + (lane & 3) * 2;
                    if (ni < cnt && c0 < HID) {
                        float bb0 = b2v[c0], bb1 = b2v[c0 + 1];
                        float w30 = w3v[c0], w31 = w3v[c0 + 1];
                        #pragma unroll
                        for (int mi = 0; mi < 2; mi++) {
                            float v0 = fmaxf(acc[mi][ni][0] + bb0, 0.f);
                            float v1 = fmaxf(acc[mi][ni][1] + bb1, 0.f);
                            float v2 = fmaxf(acc[mi][ni][2] + bb0, 0.f);
                            float v3 = fmaxf(acc[mi][ni][3] + bb1, 0.f);
                            rp[mi][0] = fmaf(w30, v0, fmaf(w31, v1, rp[mi][0]));
                            rp[mi][1] = fmaf(w30, v2, fmaf(w31, v3, rp[mi][1]));
                        }
                    }
                }
                #pragma unroll
                for (int mi = 0; mi < 2; mi++) {
                    #pragma unroll
                    for (int e = 0; e < 2; e++) {
                        rp[mi][e] += __shfl_xor_sync(0xffffffffu, rp[mi][e], 1);
                        rp[mi][e] += __shfl_xor_sync(0xffffffffu, rp[mi][e], 2);
                    }
                }
                if ((lane & 3) == 0) {
                    #pragma unroll
                    for (int mi = 0; mi < 2; mi++) {
                        int r0 = (wm * 2 + mi) * 16 + (lane >> 2);
                        redp[r0 * 2 + wnl] = rp[mi][0];
                        redp[(r0 + 8) * 2 + wnl] = rp[mi][1];
                    }
                }
                bar_q(wm);   // this quarter's redv rows complete
                if (t6 < 32) {
                    int r = wm * 32 + t6;          // own-quarter row
                    int row = tile * TILEM + r;
                    int j = row % NQ;
                    float out = redp[r * 2] + redp[r * 2 + 1] + b3;
                    float dz = (out > 0.f) ? (out + 1.f) : expf(out);
                    dzbase[(size_t)k * ROWSK + row] = dz * g_ccw[j];
                }
                // no trailing sync: redv parity buffer protects reuse
            }
        }
    }
}

// ---------------- reduction: warp per sample; blockIdx.y picks stream --------
__global__ void reduce_pair(const float* __restrict__ dzA, const float* __restrict__ xA,
                            int kA, float* __restrict__ dstA,
                            const float* __restrict__ dzB, const float* __restrict__ xB,
                            int kB, float* __restrict__ dstB)
{
    const float* dzk = (blockIdx.y == 0) ? dzA : dzB;
    const float* xin = (blockIdx.y == 0) ? xA : xB;
    float* dst       = (blockIdx.y == 0) ? dstA : dstB;
    int k            = (blockIdx.y == 0) ? kA : kB;

    int n = blockIdx.x * (blockDim.x >> 5) + (threadIdx.x >> 5);
    int lane = threadIdx.x & 31;
    if (n >= NS) return;
    const float* p = dzk + (size_t)n * NQ;
    float s = 0.f;
    for (int j = lane; j < NQ; j += 32) s += p[j];
    #pragma unroll
    for (int o = 16; o; o >>= 1) s += __shfl_xor_sync(0xffffffffu, s, o);
    if (lane == 0) {
        float z = s * xin[n] * 0.5f;
        dst[n] = expf(g_oh[k][1]) * z + g_oh[k][0];
    }
}

// ---------------- launch -----------------------------------------------------
extern "C" void kernel_launch(void* const* d_in, const int* in_sizes, int n_in,
                              void* d_out, int out_size)
{
    const float* logits = (const float*)d_in[0];
    const float* iW0 = (const float*)d_in[2];
    const float* ib0 = (const float*)d_in[3];
    const float* iW1 = (const float*)d_in[4];
    const float* ib1 = (const float*)d_in[5];
    const float* iW2 = (const float*)d_in[6];
    const float* ib2 = (const float*)d_in[7];
    const float* iW3 = (const float*)d_in[8];
    const float* ib3 = (const float*)d_in[9];
    const float* hb0 = (const float*)d_in[11];
    const float* hW1 = (const float*)d_in[12];
    const float* hb1 = (const float*)d_in[13];
    const float* hW2 = (const float*)d_in[14];
    const float* hb2 = (const float*)d_in[15];
    const float* hW3 = (const float*)d_in[16];
    const float* hb3 = (const float*)d_in[17];

    float* out = (float*)d_out;

    void *dz_addr = nullptr, *x2_addr = nullptr;
    cudaGetSymbolAddress(&dz_addr, g_dz);
    cudaGetSymbolAddress(&x2_addr, g_x2);
    float* dz = (float*)dz_addr;
    float* x2 = (float*)x2_addr;

    cudaFuncSetAttribute(mlp_tc, cudaFuncAttributeMaxDynamicSharedMemorySize, SMEM_ALLOC);

    // 1) constants (4 parallel blocks)
    setup_kernel<<<4, 128>>>(hb0, hW1, hb1, hW2, hb2, hW3, hb3);

    // 2) networks 0 and 1 on x1 = logits (2 CTAs/SM resident)
    dim3 g1(148, 2);
    mlp_tc<<<g1, MLP_T, SMEM_ALLOC>>>(logits, 0,
                                      iW0, ib0, iW1, ib1, iW2, ib2, iW3, ib3, dz);

    // 3) fused reduce: k=0 -> x2 and k=1 -> y1
    const int RWARPS = 8;
    dim3 gr((NS + RWARPS - 1) / RWARPS, 2);
    reduce_pair<<<gr, RWARPS * 32>>>(dz + 0 * (size_t)ROWSK, logits, 0, x2,
                                     dz + 1 * (size_t)ROWSK, logits, 1, out);

    // 4) network 2 on x2 (fill both CTA slots per SM)
    dim3 g2(296, 1);
    mlp_tc<<<g2, MLP_T, SMEM_ALLOC>>>(x2, 2,
                                      iW0, ib0, iW1, ib1, iW2, ib2, iW3, ib3, dz);

    // 5) reduce k=2 -> y2
    dim3 gr2((NS + RWARPS - 1) / RWARPS, 1);
    reduce_pair<<<gr2, RWARPS * 32>>>(dz + 2 * (size_t)ROWSK, x2, 2, out + NS,
                                      dz + 2 * (size_t)ROWSK, x2, 2, out + NS);

    // 6) pass-through logits
    cudaMemcpyAsync(out + 2 * NS, logits, NS * sizeof(float), cudaMemcpyDeviceToDevice);
}